// round 15
// baseline (speedup 1.0000x reference)
#include <cuda_runtime.h>

// Problem constants (fixed by the dataset)
#define PB   2      // batch
#define PN   2048   // atoms
#define PM   64     // neighbors
#define PF   128    // features
#define PH1  64
#define PH2  64

#define NW   8      // warps per MLP block
#define APW  2      // atoms per warp
#define APB  (NW * APW)   // atoms per block = 16

// float4 row strides for weight tiles (odd -> conflict-free both directions)
#define W0Q  33     // float4 per W0 row (132 floats)
#define W1Q  17     // float4 per W1 row (68 floats)

// Scratch (allocation-free rule: __device__ globals)
__device__ float g_grad[PB * PN * PF];   // dEi/dx per atom, 4 MB (L2-resident)
__device__ float g_Ei[PB * PN];          // per-atom energies

// cp.async helpers (16-byte, cache-global)
__device__ __forceinline__ void cp_async16(void* smem_dst, const void* gmem_src) {
    unsigned s = (unsigned)__cvta_generic_to_shared(smem_dst);
    asm volatile("cp.async.cg.shared.global [%0], [%1], 16;" :: "r"(s), "l"(gmem_src));
}
#define CP_COMMIT() asm volatile("cp.async.commit_group;")
#define CP_WAIT0()  asm volatile("cp.async.wait_group 0;")

// ---------------------------------------------------------------------------
// Kernel 1: warp-private MLP fwd + analytic input-gradient bwd.
// Weights in float4 rows (stride W0Q/W1Q float4): forward reads are LDS.128
// (4x fewer instructions, conflict-free per quarter-warp phase: bank
// (4l+4fq)%32); backward scalar column reads at stride 132/68 floats hit
// bank (4j+l)%32 — also conflict-free. NW=8/APW=2 = 2048 warps.
// ---------------------------------------------------------------------------
__global__ void __launch_bounds__(NW * 32) mlp_kernel(
    const float* __restrict__ image,
    const float* __restrict__ W0,     // [H1, F]
    const float* __restrict__ W1,     // [H2, H1]
    const float* __restrict__ Wout)   // [1, H2]
{
    extern __shared__ float dyn[];
    float4* sW0q = (float4*)dyn;                    // 64*33 float4
    float4* sW1q = sW0q + PH1 * W0Q;                // 64*17 float4
    float*  sX   = (float*)(sW1q + PH2 * W1Q);      // NW*APW*PF floats
    float*  sBuf = sX + NW * APW * PF;              // NW*APW*PH1 floats
    float*  sWo  = sBuf + NW * APW * PH1;           // 64

    const float* sW0f = (const float*)sW0q;         // scalar view, row stride 132
    const float* sW1f = (const float*)sW1q;         // scalar view, row stride 68

    const int tid = threadIdx.x;
    const int w   = tid >> 5;
    const int l   = tid & 31;

    // ---- stage weights: float4 in, float4 out (aligned, coalesced) ----
    {
        const float4* w0v = (const float4*)W0;
        for (int i = tid; i < (PH1 * PF) / 4; i += NW * 32) {
            const int idx = i * 4;
            sW0q[(idx >> 7) * W0Q + ((idx & 127) >> 2)] = w0v[i];
        }
        const float4* w1v = (const float4*)W1;
        for (int i = tid; i < (PH2 * PH1) / 4; i += NW * 32) {
            const int idx = i * 4;
            sW1q[(idx >> 6) * W1Q + ((idx & 63) >> 2)] = w1v[i];
        }
    }
    if (tid < PH2) sWo[tid] = Wout[tid];
    __syncthreads();

    const int a0 = blockIdx.x * APB + w * APW;
    float* wX = sX + w * (APW * PF);
    float* wB = sBuf + w * (APW * PH1);

    // ---- stage x for APW atoms: contiguous float4, conflict-free ----
    {
        const float4* src = (const float4*)(image + (size_t)a0 * PF);
        float4* dst = (float4*)wX;
        #pragma unroll
        for (int it = 0; it < APW; it++) dst[it * 32 + l] = src[it * 32 + l];
    }
    __syncwarp();

    const float4* w0aq = sW0q + l * W0Q;
    const float4* w0bq = sW0q + (l + 32) * W0Q;
    const float4* w1aq = sW1q + l * W1Q;
    const float4* w1bq = sW1q + (l + 32) * W1Q;

    // ---- L0 forward: h0[j] = sigmoid(sum_f W0[j,f] x[f]), j = l, l+32 ----
    float h0v[2][APW];
    {
        float acc[2][APW];
        #pragma unroll
        for (int h = 0; h < 2; h++)
            #pragma unroll
            for (int at = 0; at < APW; at++) acc[h][at] = 0.f;

        #pragma unroll 4
        for (int fq = 0; fq < PF / 4; fq++) {
            const float4 wa4 = w0aq[fq];            // LDS.128
            const float4 wb4 = w0bq[fq];
            #pragma unroll
            for (int at = 0; at < APW; at++) {
                const float4 xv = *(const float4*)(wX + at * PF + fq * 4);
                acc[0][at] += wa4.x * xv.x + wa4.y * xv.y + wa4.z * xv.z + wa4.w * xv.w;
                acc[1][at] += wb4.x * xv.x + wb4.y * xv.y + wb4.z * xv.z + wb4.w * xv.w;
            }
        }
        #pragma unroll
        for (int h = 0; h < 2; h++)
            #pragma unroll
            for (int at = 0; at < APW; at++)
                h0v[h][at] = 1.f / (1.f + __expf(-acc[h][at]));
    }
    #pragma unroll
    for (int at = 0; at < APW; at++) {
        wB[at * PH1 + l]      = h0v[0][at];
        wB[at * PH1 + l + 32] = h0v[1][at];
    }
    __syncwarp();

    // ---- L1 forward: h1[k] = sigmoid(sum_j W1[k,j] h0[j]), k = l, l+32 ----
    float h1v[2][APW];
    {
        float acc[2][APW];
        #pragma unroll
        for (int h = 0; h < 2; h++)
            #pragma unroll
            for (int at = 0; at < APW; at++) acc[h][at] = 0.f;

        #pragma unroll 4
        for (int jq = 0; jq < PH1 / 4; jq++) {
            const float4 wa4 = w1aq[jq];            // LDS.128
            const float4 wb4 = w1bq[jq];
            #pragma unroll
            for (int at = 0; at < APW; at++) {
                const float4 hv = *(const float4*)(wB + at * PH1 + jq * 4);
                acc[0][at] += wa4.x * hv.x + wa4.y * hv.y + wa4.z * hv.z + wa4.w * hv.w;
                acc[1][at] += wb4.x * hv.x + wb4.y * hv.y + wb4.z * hv.z + wb4.w * hv.w;
            }
        }
        #pragma unroll
        for (int h = 0; h < 2; h++)
            #pragma unroll
            for (int at = 0; at < APW; at++)
                h1v[h][at] = 1.f / (1.f + __expf(-acc[h][at]));
    }

    // ---- Ei = sum_k h1[k]*Wout[k] (deterministic warp shuffle reduce) ----
    const float wo0 = sWo[l], wo1 = sWo[l + 32];
    #pragma unroll
    for (int at = 0; at < APW; at++) {
        float v = h1v[0][at] * wo0 + h1v[1][at] * wo1;
        #pragma unroll
        for (int o = 16; o; o >>= 1) v += __shfl_down_sync(0xffffffffu, v, o);
        if (l == 0) g_Ei[a0 + at] = v;
    }
    __syncwarp();

    // ---- t1 = h1*(1-h1)*Wout -> publish (overwrites h0 buffer) ----
    #pragma unroll
    for (int at = 0; at < APW; at++) {
        wB[at * PH1 + l]      = h1v[0][at] * (1.f - h1v[0][at]) * wo0;
        wB[at * PH1 + l + 32] = h1v[1][at] * (1.f - h1v[1][at]) * wo1;
    }
    __syncwarp();

    // ---- gH1[j] = sum_k t1[k]*W1[k,j]; t0 = h0*(1-h0)*gH1, j = l, l+32 ----
    float t0v[2][APW];
    {
        float acc[2][APW];
        #pragma unroll
        for (int h = 0; h < 2; h++)
            #pragma unroll
            for (int at = 0; at < APW; at++) acc[h][at] = 0.f;

        #pragma unroll 4
        for (int k = 0; k < PH2; k += 4) {
            float4 tv[APW];
            #pragma unroll
            for (int at = 0; at < APW; at++)
                tv[at] = *(const float4*)(wB + at * PH1 + k);
            #pragma unroll
            for (int kk = 0; kk < 4; kk++) {
                // column read: bank (4(k+kk) + l) % 32 distinct per lane
                const float wa = sW1f[(k + kk) * (W1Q * 4) + l];
                const float wb = sW1f[(k + kk) * (W1Q * 4) + l + 32];
                #pragma unroll
                for (int at = 0; at < APW; at++) {
                    const float te = ((const float*)&tv[at])[kk];
                    acc[0][at] += wa * te;
                    acc[1][at] += wb * te;
                }
            }
        }
        #pragma unroll
        for (int h = 0; h < 2; h++)
            #pragma unroll
            for (int at = 0; at < APW; at++)
                t0v[h][at] = h0v[h][at] * (1.f - h0v[h][at]) * acc[h][at];
    }
    __syncwarp();

    // ---- publish t0 ----
    #pragma unroll
    for (int at = 0; at < APW; at++) {
        wB[at * PH1 + l]      = t0v[0][at];
        wB[at * PH1 + l + 32] = t0v[1][at];
    }
    __syncwarp();

    // ---- g[f] = sum_j t0[j]*W0[j,f], f = l + 32q ----
    {
        float acc[4][APW];
        #pragma unroll
        for (int q = 0; q < 4; q++)
            #pragma unroll
            for (int at = 0; at < APW; at++) acc[q][at] = 0.f;

        for (int j = 0; j < PH1; j += 4) {
            float4 tv[APW];
            #pragma unroll
            for (int at = 0; at < APW; at++)
                tv[at] = *(const float4*)(wB + at * PH1 + j);
            #pragma unroll
            for (int jj = 0; jj < 4; jj++) {
                const float* wrow = sW0f + (j + jj) * (W0Q * 4) + l;
                #pragma unroll
                for (int q = 0; q < 4; q++) {
                    const float wv = wrow[32 * q];   // bank (4j + l) % 32 distinct
                    #pragma unroll
                    for (int at = 0; at < APW; at++)
                        acc[q][at] += wv * ((const float*)&tv[at])[jj];
                }
            }
        }
        #pragma unroll
        for (int at = 0; at < APW; at++)
            #pragma unroll
            for (int q = 0; q < 4; q++)
                g_grad[(size_t)(a0 + at) * PF + l + 32 * q] = acc[q][at];
    }
}

// ---------------------------------------------------------------------------
// Kernel 2: deterministic Etot reduction (no float atomics)
// ---------------------------------------------------------------------------
__global__ void etot_kernel(float* __restrict__ out)
{
    const int b = blockIdx.x;
    const int tid = threadIdx.x;
    __shared__ float sm[256];
    float s = 0.f;
    for (int i = tid; i < PN; i += 256) s += g_Ei[b * PN + i];
    sm[tid] = s;
    __syncthreads();
    #pragma unroll
    for (int o = 128; o; o >>= 1) {
        if (tid < o) sm[tid] += sm[tid + o];
        __syncthreads();
    }
    if (tid == 0) out[b] = sm[0];
}

// ---------------------------------------------------------------------------
// Kernel 3: force via cp.async double-buffered pipeline. (round-11 WIN, unchanged)
// ---------------------------------------------------------------------------
__global__ void __launch_bounds__(128) force_kernel(
    const float* __restrict__ dfeat,
    const int*   __restrict__ neighbor,
    float*       __restrict__ out)     // out[0..1]=Etot, force at out+2
{
    const int bn  = blockIdx.x;        // 0 .. B*N-1
    const int b   = bn >> 11;          // / PN
    const int tid = threadIdx.x;

    __shared__ float4 buf4[2][768];    // 2 x 12 KB dfeat chunks (8 rows x 384 f)
    __shared__ float4 gs4[2][256];     // 2 x 4 KB g chunks (8 rows x 128 f)
    __shared__ int    sidx[PM];
    __shared__ float  sred[4][3];

    if (tid < PM) sidx[tid] = neighbor[bn * PM + tid];
    __syncthreads();

    const float4* df4 = (const float4*)(dfeat + (size_t)bn * (PM * PF * 3));
    const float4* g4  = (const float4*)(g_grad + (size_t)b * PN * PF);

    float4 rg[2];

    // ---- prologue: chunk 0 ----
    #pragma unroll
    for (int k = 0; k < 6; k++)
        cp_async16(&buf4[0][k * 128 + tid], &df4[k * 128 + tid]);
    CP_COMMIT();
    #pragma unroll
    for (int k = 0; k < 2; k++) {
        const int q = k * 128 + tid;
        const int ml = q >> 5, c2 = q & 31;    // warp-uniform row, lane = col
        const int nv = sidx[ml];
        rg[k] = (nv > 0) ? g4[(size_t)(nv - 1) * 32 + c2]
                         : make_float4(0.f, 0.f, 0.f, 0.f);
    }
    #pragma unroll
    for (int k = 0; k < 2; k++) gs4[0][k * 128 + tid] = rg[k];
    CP_WAIT0();
    __syncthreads();

    float ax = 0.f, ay = 0.f, az = 0.f;

    #pragma unroll
    for (int c = 0; c < 8; c++) {
        const int cur = c & 1;
        if (c < 7) {   // issue async loads for chunk c+1
            #pragma unroll
            for (int k = 0; k < 6; k++)
                cp_async16(&buf4[cur ^ 1][k * 128 + tid],
                           &df4[(c + 1) * 768 + k * 128 + tid]);
            CP_COMMIT();
            #pragma unroll
            for (int k = 0; k < 2; k++) {
                const int q = k * 128 + tid;
                const int ml = q >> 5, c2 = q & 31;
                const int nv = sidx[(c + 1) * 8 + ml];
                rg[k] = (nv > 0) ? g4[(size_t)(nv - 1) * 32 + c2]
                                 : make_float4(0.f, 0.f, 0.f, 0.f);
            }
        }

        // consume chunk c: uniform indexing, no divergence
        const float* bb = (const float*)buf4[cur];
        const float* gg = (const float*)gs4[cur];
        #pragma unroll
        for (int mm = 0; mm < 8; mm++) {
            const float gv = gg[mm * 128 + tid];          // banks tid%32
            const float* row = bb + mm * 384 + tid * 3;   // banks (3*tid)%32
            ax += gv * row[0];
            ay += gv * row[1];
            az += gv * row[2];
        }

        if (c < 7) {
            #pragma unroll
            for (int k = 0; k < 2; k++) gs4[cur ^ 1][k * 128 + tid] = rg[k];
        }
        CP_WAIT0();
        __syncthreads();
    }

    // reduce 128 threads -> 3 floats
    #pragma unroll
    for (int o = 16; o; o >>= 1) {
        ax += __shfl_down_sync(0xffffffffu, ax, o);
        ay += __shfl_down_sync(0xffffffffu, ay, o);
        az += __shfl_down_sync(0xffffffffu, az, o);
    }
    const int w = tid >> 5, l = tid & 31;
    if (l == 0) { sred[w][0] = ax; sred[w][1] = ay; sred[w][2] = az; }
    __syncthreads();
    if (tid < 3) {
        const float v = sred[0][tid] + sred[1][tid] + sred[2][tid] + sred[3][tid];
        out[2 + bn * 3 + tid] = v * 1e10f;
    }
}

// ---------------------------------------------------------------------------
extern "C" void kernel_launch(void* const* d_in, const int* in_sizes, int n_in,
                              void* d_out, int out_size)
{
    const float* image    = (const float*)d_in[0];
    const float* dfeat    = (const float*)d_in[1];
    const int*   neighbor = (const int*)  d_in[2];
    // d_in[3] Egroup_weight, d_in[4] divider: unused by the reference math
    const float* W0       = (const float*)d_in[5];
    const float* W1       = (const float*)d_in[6];
    const float* Wout     = (const float*)d_in[7];
    float* out = (float*)d_out;

    const int smem_bytes = (PH1 * W0Q * 4 + PH2 * W1Q * 4 + NW * APW * PF
                            + NW * APW * PH1 + PH2) * 4;
    cudaFuncSetAttribute(mlp_kernel, cudaFuncAttributeMaxDynamicSharedMemorySize, smem_bytes);

    mlp_kernel<<<(PB * PN) / APB, NW * 32, smem_bytes>>>(image, W0, W1, Wout);
    etot_kernel<<<PB, 256>>>(out);
    force_kernel<<<PB * PN, 128>>>(dfeat, neighbor, out);
}

// round 16
// speedup vs baseline: 1.2388x; 1.2388x over previous
#include <cuda_runtime.h>

// Problem constants (fixed by the dataset)
#define PB   2      // batch
#define PN   2048   // atoms
#define PM   64     // neighbors
#define PF   128    // features
#define PH1  64
#define PH2  64

#define NW   8      // warps per MLP block
#define APW  2      // atoms per warp
#define APB  (NW * APW)   // atoms per block = 16

// Padded weight row strides (conflict-free banks without index math)
#define W0S  129    // (129*l + f) % 32 == (l+f)%32 -> distinct per lane
#define W1S  65

// Scratch (allocation-free rule: __device__ globals)
__device__ float g_grad[PB * PN * PF];   // dEi/dx per atom, 4 MB (L2-resident)
__device__ float g_Ei[PB * PN];          // per-atom energies

// cp.async helpers (16-byte, cache-global)
__device__ __forceinline__ void cp_async16(void* smem_dst, const void* gmem_src) {
    unsigned s = (unsigned)__cvta_generic_to_shared(smem_dst);
    asm volatile("cp.async.cg.shared.global [%0], [%1], 16;" :: "r"(s), "l"(gmem_src));
}
#define CP_COMMIT() asm volatile("cp.async.commit_group;")
#define CP_WAIT0()  asm volatile("cp.async.wait_group 0;")

// ---------------------------------------------------------------------------
// Kernel 1: warp-private MLP fwd + analytic input-gradient bwd. (round-13
// measured best; launch_bounds minBlocks=1 lets ptxas use more registers
// for ILP in the latency-bound GEMV chains.)
// ---------------------------------------------------------------------------
__global__ void __launch_bounds__(NW * 32, 1) mlp_kernel(
    const float* __restrict__ image,
    const float* __restrict__ W0,     // [H1, F]
    const float* __restrict__ W1,     // [H2, H1]
    const float* __restrict__ Wout)   // [1, H2]
{
    extern __shared__ float dyn[];
    float* sW0  = dyn;                     // 64*129 floats, padded rows
    float* sW1  = sW0 + PH1 * W0S;         // 64*65 floats, padded rows
    float* sX   = sW1 + PH2 * W1S;         // NW*APW*PF, plain [at][f]
    float* sBuf = sX + NW * APW * PF;      // NW*APW*PH1, plain [at][j]
    float* sWo  = sBuf + NW * APW * PH1;   // 64

    const int tid = threadIdx.x;
    const int w   = tid >> 5;
    const int l   = tid & 31;

    // ---- stage weights: float4 global reads, scalar padded stores ----
    {
        const float4* w0v = (const float4*)W0;
        for (int i = tid; i < (PH1 * PF) / 4; i += NW * 32) {
            const float4 v = w0v[i];
            const int idx = i * 4;
            float* dst = sW0 + (idx >> 7) * W0S + (idx & 127);
            dst[0] = v.x; dst[1] = v.y; dst[2] = v.z; dst[3] = v.w;
        }
        const float4* w1v = (const float4*)W1;
        for (int i = tid; i < (PH2 * PH1) / 4; i += NW * 32) {
            const float4 v = w1v[i];
            const int idx = i * 4;
            float* dst = sW1 + (idx >> 6) * W1S + (idx & 63);
            dst[0] = v.x; dst[1] = v.y; dst[2] = v.z; dst[3] = v.w;
        }
    }
    if (tid < PH2) sWo[tid] = Wout[tid];
    __syncthreads();

    const int a0 = blockIdx.x * APB + w * APW;
    float* wX = sX + w * (APW * PF);
    float* wB = sBuf + w * (APW * PH1);

    // ---- stage x for APW atoms: contiguous float4, conflict-free ----
    {
        const float4* src = (const float4*)(image + (size_t)a0 * PF);
        float4* dst = (float4*)wX;
        #pragma unroll
        for (int it = 0; it < APW; it++) dst[it * 32 + l] = src[it * 32 + l];
    }
    __syncwarp();

    const float* w0a = sW0 + l * W0S;
    const float* w0b = sW0 + (l + 32) * W0S;
    const float* w1a = sW1 + l * W1S;
    const float* w1b = sW1 + (l + 32) * W1S;

    // ---- L0 forward: h0[j] = sigmoid(sum_f W0[j,f] x[f]), j = l, l+32 ----
    float h0v[2][APW];
    {
        float acc[2][APW];
        #pragma unroll
        for (int h = 0; h < 2; h++)
            #pragma unroll
            for (int at = 0; at < APW; at++) acc[h][at] = 0.f;

        #pragma unroll 4
        for (int f = 0; f < PF; f += 4) {
            float4 xv[APW];
            #pragma unroll
            for (int at = 0; at < APW; at++)
                xv[at] = *(const float4*)(wX + at * PF + f);
            #pragma unroll
            for (int ff = 0; ff < 4; ff++) {
                const float wa = w0a[f + ff];
                const float wb = w0b[f + ff];
                #pragma unroll
                for (int at = 0; at < APW; at++) {
                    const float xe = ((const float*)&xv[at])[ff];
                    acc[0][at] += wa * xe;
                    acc[1][at] += wb * xe;
                }
            }
        }
        #pragma unroll
        for (int h = 0; h < 2; h++)
            #pragma unroll
            for (int at = 0; at < APW; at++)
                h0v[h][at] = 1.f / (1.f + __expf(-acc[h][at]));
    }
    #pragma unroll
    for (int at = 0; at < APW; at++) {
        wB[at * PH1 + l]      = h0v[0][at];
        wB[at * PH1 + l + 32] = h0v[1][at];
    }
    __syncwarp();

    // ---- L1 forward: h1[k] = sigmoid(sum_j W1[k,j] h0[j]), k = l, l+32 ----
    float h1v[2][APW];
    {
        float acc[2][APW];
        #pragma unroll
        for (int h = 0; h < 2; h++)
            #pragma unroll
            for (int at = 0; at < APW; at++) acc[h][at] = 0.f;

        #pragma unroll 4
        for (int j = 0; j < PH1; j += 4) {
            float4 hv[APW];
            #pragma unroll
            for (int at = 0; at < APW; at++)
                hv[at] = *(const float4*)(wB + at * PH1 + j);
            #pragma unroll
            for (int ff = 0; ff < 4; ff++) {
                const float wa = w1a[j + ff];
                const float wb = w1b[j + ff];
                #pragma unroll
                for (int at = 0; at < APW; at++) {
                    const float he = ((const float*)&hv[at])[ff];
                    acc[0][at] += wa * he;
                    acc[1][at] += wb * he;
                }
            }
        }
        #pragma unroll
        for (int h = 0; h < 2; h++)
            #pragma unroll
            for (int at = 0; at < APW; at++)
                h1v[h][at] = 1.f / (1.f + __expf(-acc[h][at]));
    }

    // ---- Ei = sum_k h1[k]*Wout[k] (deterministic warp shuffle reduce) ----
    const float wo0 = sWo[l], wo1 = sWo[l + 32];
    #pragma unroll
    for (int at = 0; at < APW; at++) {
        float v = h1v[0][at] * wo0 + h1v[1][at] * wo1;
        #pragma unroll
        for (int o = 16; o; o >>= 1) v += __shfl_down_sync(0xffffffffu, v, o);
        if (l == 0) g_Ei[a0 + at] = v;
    }
    __syncwarp();

    // ---- t1 = h1*(1-h1)*Wout -> publish (overwrites h0 buffer) ----
    #pragma unroll
    for (int at = 0; at < APW; at++) {
        wB[at * PH1 + l]      = h1v[0][at] * (1.f - h1v[0][at]) * wo0;
        wB[at * PH1 + l + 32] = h1v[1][at] * (1.f - h1v[1][at]) * wo1;
    }
    __syncwarp();

    // ---- gH1[j] = sum_k t1[k]*W1[k,j]; t0 = h0*(1-h0)*gH1, j = l, l+32 ----
    float t0v[2][APW];
    {
        float acc[2][APW];
        #pragma unroll
        for (int h = 0; h < 2; h++)
            #pragma unroll
            for (int at = 0; at < APW; at++) acc[h][at] = 0.f;

        #pragma unroll 4
        for (int k = 0; k < PH2; k += 4) {
            float4 tv[APW];
            #pragma unroll
            for (int at = 0; at < APW; at++)
                tv[at] = *(const float4*)(wB + at * PH1 + k);
            #pragma unroll
            for (int kk = 0; kk < 4; kk++) {
                // column read of padded W1: banks (k*65 + l) % 32 distinct
                const float wa = sW1[(k + kk) * W1S + l];
                const float wb = sW1[(k + kk) * W1S + l + 32];
                #pragma unroll
                for (int at = 0; at < APW; at++) {
                    const float te = ((const float*)&tv[at])[kk];
                    acc[0][at] += wa * te;
                    acc[1][at] += wb * te;
                }
            }
        }
        #pragma unroll
        for (int h = 0; h < 2; h++)
            #pragma unroll
            for (int at = 0; at < APW; at++)
                t0v[h][at] = h0v[h][at] * (1.f - h0v[h][at]) * acc[h][at];
    }
    __syncwarp();

    // ---- publish t0 ----
    #pragma unroll
    for (int at = 0; at < APW; at++) {
        wB[at * PH1 + l]      = t0v[0][at];
        wB[at * PH1 + l + 32] = t0v[1][at];
    }
    __syncwarp();

    // ---- g[f] = sum_j t0[j]*W0[j,f], f = l + 32q ----
    {
        float acc[4][APW];
        #pragma unroll
        for (int q = 0; q < 4; q++)
            #pragma unroll
            for (int at = 0; at < APW; at++) acc[q][at] = 0.f;

        for (int j = 0; j < PH1; j += 4) {
            float4 tv[APW];
            #pragma unroll
            for (int at = 0; at < APW; at++)
                tv[at] = *(const float4*)(wB + at * PH1 + j);
            #pragma unroll
            for (int jj = 0; jj < 4; jj++) {
                const float* wrow = sW0 + (j + jj) * W0S + l;
                #pragma unroll
                for (int q = 0; q < 4; q++) {
                    const float wv = wrow[32 * q];   // banks (j + l) % 32 distinct
                    #pragma unroll
                    for (int at = 0; at < APW; at++)
                        acc[q][at] += wv * ((const float*)&tv[at])[jj];
                }
            }
        }
        #pragma unroll
        for (int at = 0; at < APW; at++)
            #pragma unroll
            for (int q = 0; q < 4; q++)
                g_grad[(size_t)(a0 + at) * PF + l + 32 * q] = acc[q][at];
    }
}

// ---------------------------------------------------------------------------
// Kernel 2: force via cp.async double-buffered pipeline (round-11/13 best).
// Blocks 0 and 1 additionally compute Etot for batch 0/1 (first-wave blocks;
// the extra reduction hides under the 66 us memory stream) — etot kernel gone.
// ---------------------------------------------------------------------------
__global__ void __launch_bounds__(128) force_kernel(
    const float* __restrict__ dfeat,
    const int*   __restrict__ neighbor,
    float*       __restrict__ out)     // out[0..1]=Etot, force at out+2
{
    const int bn  = blockIdx.x;        // 0 .. B*N-1
    const int b   = bn >> 11;          // / PN
    const int tid = threadIdx.x;

    __shared__ float4 buf4[2][768];    // 2 x 12 KB dfeat chunks (8 rows x 384 f)
    __shared__ float4 gs4[2][256];     // 2 x 4 KB g chunks (8 rows x 128 f)
    __shared__ int    sidx[PM];
    __shared__ float  sred[4][3];
    __shared__ float  esm[128];

    if (tid < PM) sidx[tid] = neighbor[bn * PM + tid];
    __syncthreads();

    const float4* df4 = (const float4*)(dfeat + (size_t)bn * (PM * PF * 3));
    const float4* g4  = (const float4*)(g_grad + (size_t)b * PN * PF);

    float4 rg[2];

    // ---- prologue: chunk 0 ----
    #pragma unroll
    for (int k = 0; k < 6; k++)
        cp_async16(&buf4[0][k * 128 + tid], &df4[k * 128 + tid]);
    CP_COMMIT();
    #pragma unroll
    for (int k = 0; k < 2; k++) {
        const int q = k * 128 + tid;
        const int ml = q >> 5, c2 = q & 31;    // warp-uniform row, lane = col
        const int nv = sidx[ml];
        rg[k] = (nv > 0) ? g4[(size_t)(nv - 1) * 32 + c2]
                         : make_float4(0.f, 0.f, 0.f, 0.f);
    }
    #pragma unroll
    for (int k = 0; k < 2; k++) gs4[0][k * 128 + tid] = rg[k];

    // ---- Etot side-job for blocks 0/1 (overlaps with cp.async in flight) ----
    if (bn < PB) {
        float s = 0.f;
        for (int i = tid; i < PN; i += 128) s += g_Ei[bn * PN + i];
        esm[tid] = s;
        __syncthreads();
        #pragma unroll
        for (int o = 64; o; o >>= 1) {
            if (tid < o) esm[tid] += esm[tid + o];
            __syncthreads();
        }
        if (tid == 0) out[bn] = esm[0];
    }

    CP_WAIT0();
    __syncthreads();

    float ax = 0.f, ay = 0.f, az = 0.f;

    #pragma unroll
    for (int c = 0; c < 8; c++) {
        const int cur = c & 1;
        if (c < 7) {   // issue async loads for chunk c+1
            #pragma unroll
            for (int k = 0; k < 6; k++)
                cp_async16(&buf4[cur ^ 1][k * 128 + tid],
                           &df4[(c + 1) * 768 + k * 128 + tid]);
            CP_COMMIT();
            #pragma unroll
            for (int k = 0; k < 2; k++) {
                const int q = k * 128 + tid;
                const int ml = q >> 5, c2 = q & 31;
                const int nv = sidx[(c + 1) * 8 + ml];
                rg[k] = (nv > 0) ? g4[(size_t)(nv - 1) * 32 + c2]
                                 : make_float4(0.f, 0.f, 0.f, 0.f);
            }
        }

        // consume chunk c: uniform indexing, no divergence
        const float* bb = (const float*)buf4[cur];
        const float* gg = (const float*)gs4[cur];
        #pragma unroll
        for (int mm = 0; mm < 8; mm++) {
            const float gv = gg[mm * 128 + tid];          // banks tid%32
            const float* row = bb + mm * 384 + tid * 3;   // banks (3*tid)%32
            ax += gv * row[0];
            ay += gv * row[1];
            az += gv * row[2];
        }

        if (c < 7) {
            #pragma unroll
            for (int k = 0; k < 2; k++) gs4[cur ^ 1][k * 128 + tid] = rg[k];
        }
        CP_WAIT0();
        __syncthreads();
    }

    // reduce 128 threads -> 3 floats
    #pragma unroll
    for (int o = 16; o; o >>= 1) {
        ax += __shfl_down_sync(0xffffffffu, ax, o);
        ay += __shfl_down_sync(0xffffffffu, ay, o);
        az += __shfl_down_sync(0xffffffffu, az, o);
    }
    const int w = tid >> 5, l = tid & 31;
    if (l == 0) { sred[w][0] = ax; sred[w][1] = ay; sred[w][2] = az; }
    __syncthreads();
    if (tid < 3) {
        const float v = sred[0][tid] + sred[1][tid] + sred[2][tid] + sred[3][tid];
        out[2 + bn * 3 + tid] = v * 1e10f;
    }
}

// ---------------------------------------------------------------------------
extern "C" void kernel_launch(void* const* d_in, const int* in_sizes, int n_in,
                              void* d_out, int out_size)
{
    const float* image    = (const float*)d_in[0];
    const float* dfeat    = (const float*)d_in[1];
    const int*   neighbor = (const int*)  d_in[2];
    // d_in[3] Egroup_weight, d_in[4] divider: unused by the reference math
    const float* W0       = (const float*)d_in[5];
    const float* W1       = (const float*)d_in[6];
    const float* Wout     = (const float*)d_in[7];
    float* out = (float*)d_out;

    const int smem_bytes = (PH1 * W0S + PH2 * W1S + NW * APW * PF
                            + NW * APW * PH1 + PH2) * 4;
    cudaFuncSetAttribute(mlp_kernel, cudaFuncAttributeMaxDynamicSharedMemorySize, smem_bytes);

    mlp_kernel<<<(PB * PN) / APB, NW * 32, smem_bytes>>>(image, W0, W1, Wout);
    force_kernel<<<PB * PN, 128>>>(dfeat, neighbor, out);
}